// round 8
// baseline (speedup 1.0000x reference)
#include <cuda_runtime.h>
#include <cuda_bf16.h>
#include <stdint.h>
#include <math.h>

#define BB 2
#define LL 2048
#define DM 512
#define DI 1024
#define DS 16
#define NTOK (BB*LL)   // 4096
#define TCHUNK 32
#define CH 16

typedef unsigned short bf16raw;

static __device__ __forceinline__ bf16raw f2b(float x){
    __nv_bfloat16 h = __float2bfloat16_rn(x);
    return *reinterpret_cast<bf16raw*>(&h);
}
static __device__ __forceinline__ float b2f(bf16raw v){
    __nv_bfloat16 h = *reinterpret_cast<__nv_bfloat16*>(&v);
    return __bfloat162float(h);
}
static __device__ __forceinline__ void cp16(void* dst, const void* src){
    unsigned sa = (unsigned)__cvta_generic_to_shared(dst);
    asm volatile("cp.async.cg.shared.global [%0], [%1], 16;" :: "r"(sa), "l"(src));
}

// ---------------- scratch -------------------------------------------------
__device__ bf16raw g_xz_bf[2][NTOK*2*DI];    // in-proj out (xi|z), bf16
__device__ float   g_xdbl[2][NTOK*64];       // x_proj out fp32 (scan B/C)
__device__ bf16raw g_dt_bf[2][NTOK*DI];      // softplus(dt), bf16
__device__ float   g_dtb[2][DI];
__device__ bf16raw g_xn_bf[NTOK*DM];
__device__ bf16raw g_xi_bf[2][NTOK*DI];      // conv+silu out, bf16 (GEMM2 A + scan)
__device__ bf16raw g_xdbl_bf[2][NTOK*64];
__device__ bf16raw g_ycat_bf[NTOK*2*DI];
__device__ bf16raw g_wcomb[2*DI*DM];         // folded Wcat@Wproj [2048][512]
__device__ float   g_part[2][NTOK*DM];       // split-K partials
// bf16 weights
__device__ bf16raw g_w_in[2][DM*2*DI];
__device__ bf16raw g_w_xp[2][DI*64];
__device__ bf16raw g_w_dt[2][32*DI];
__device__ bf16raw g_w_cat[2*DI*DM];
__device__ bf16raw g_w_pj[DM*DM];

// ---------------- fused fp32 -> bf16 conversion ----------------------------
struct CvtArgs { const float* s[9]; bf16raw* d[9]; int off[10]; };

__global__ void cvt_all_kernel(CvtArgs a, int total4){
    int i = blockIdx.x*blockDim.x + threadIdx.x;
    if (i >= total4) return;
    int seg = 0;
    while (i >= a.off[seg+1]) seg++;
    int j = (i - a.off[seg])*4;
    float4 v = *(const float4*)(a.s[seg] + j);
    bf16raw* d = a.d[seg] + j;
    d[0]=f2b(v.x); d[1]=f2b(v.y); d[2]=f2b(v.z); d[3]=f2b(v.w);
}

__global__ void pack_dtb_kernel(const float* __restrict__ f, const float* __restrict__ b){
    int i = blockIdx.x*blockDim.x + threadIdx.x;
    if (i < DI)            g_dtb[0][i]    = f[i];
    else if (i < 2*DI)     g_dtb[1][i-DI] = b[i-DI];
}

// ---------------- layernorm (writes bf16) ---------------------------------
__global__ void ln_kernel(const float* __restrict__ x,
                          const float* __restrict__ g,
                          const float* __restrict__ b) {
    int row = blockIdx.x;
    const float* xr = x + (long)row*DM;
    int tid = threadIdx.x;
    float v0 = xr[tid], v1 = xr[tid+256];
    __shared__ float s1[256], s2[256];
    s1[tid] = v0+v1; s2[tid] = v0*v0+v1*v1;
    __syncthreads();
    for (int o=128;o>0;o>>=1){
        if (tid<o){ s1[tid]+=s1[tid+o]; s2[tid]+=s2[tid+o]; }
        __syncthreads();
    }
    float mu = s1[0]*(1.0f/DM);
    float var = s2[0]*(1.0f/DM) - mu*mu;
    float rs = rsqrtf(var + 1e-5f);
    g_xn_bf[(long)row*DM+tid]     = f2b((v0-mu)*rs*g[tid]     + b[tid]);
    g_xn_bf[(long)row*DM+tid+256] = f2b((v1-mu)*rs*g[tid+256] + b[tid+256]);
}

// ---------------- bf16 tensor-core GEMM, 128x128 tile, templated BK --------
template<int BK>
__global__ __launch_bounds__(256) void hgemm(
    const bf16raw* __restrict__ Ag, long sA, int lda,
    const bf16raw* __restrict__ Bg, long sB, int ldb,
    float* __restrict__ Cg, long sC, int ldc,
    bf16raw* __restrict__ Obg, long sO,
    int N, int K,
    const float* __restrict__ biasg, long sbias,
    const float* __restrict__ res, int ldres,
    int epi)
{
    const bf16raw* A = Ag + sA*blockIdx.z;
    const bf16raw* B = Bg + sB*blockIdx.z;
    float* C   = Cg  ? Cg  + sC*blockIdx.z : nullptr;
    bf16raw* Ob = Obg ? Obg + sO*blockIdx.z : nullptr;
    const float* bias = biasg ? biasg + sbias*blockIdx.z : nullptr;

    extern __shared__ __align__(16) bf16raw sdyn[];
    const int ABUF = 128*(BK+8);
    const int BBUF = BK*128;
    bf16raw* As = sdyn;
    bf16raw* Bs = sdyn + 2*ABUF;

    int tid = threadIdx.x;
    int lane = tid & 31, wid = tid >> 5;
    int warp_m = wid & 3, warp_n = wid >> 2;
    int bm = blockIdx.y*128, bn = blockIdx.x*128;

    float acc[2][8][4];
    #pragma unroll
    for (int a=0;a<2;a++) for (int b2=0;b2<8;b2++) for (int c=0;c<4;c++) acc[a][b2][c]=0.f;

    int KT = K / BK;
    const int CPR = BK/8;

    auto loadTile = [&](int kt, int buf){
        int k0 = kt*BK;
        #pragma unroll
        for (int i=0;i<BK/16;i++){
            int q = tid + i*256;
            int r = q / CPR, c = q % CPR;
            const bf16raw* src = A + (long)(bm+r)*lda + k0 + c*8;
            unsigned sa = (unsigned)__cvta_generic_to_shared(&As[buf*ABUF + r*(BK+8) + c*8]);
            asm volatile("cp.async.cg.shared.global [%0], [%1], 16;\n" :: "r"(sa), "l"(src));
        }
        #pragma unroll
        for (int i=0;i<BK/16;i++){
            int q = tid + i*256;
            int r = q>>4, c = q&15;
            int gcol = bn + c*8;
            const bf16raw* src = B + (long)(k0+r)*ldb + gcol;
            unsigned sa = (unsigned)__cvta_generic_to_shared(&Bs[buf*BBUF + r*128 + ((c ^ (r&7))*8)]);
            int sz = (gcol < N) ? 16 : 0;
            asm volatile("cp.async.cg.shared.global [%0], [%1], 16, %2;\n" :: "r"(sa), "l"(src), "r"(sz));
        }
    };

    loadTile(0, 0);
    asm volatile("cp.async.commit_group;\n" ::: "memory");

    for (int kt=0; kt<KT; kt++){
        if (kt+1 < KT) loadTile(kt+1, (kt+1)&1);
        asm volatile("cp.async.commit_group;\n" ::: "memory");
        asm volatile("cp.async.wait_group 1;\n" ::: "memory");
        __syncthreads();
        int buf = kt & 1;

        #pragma unroll
        for (int ks=0; ks<BK/16; ks++){
            unsigned af[2][4];
            #pragma unroll
            for (int mt=0; mt<2; mt++){
                int row = warp_m*32 + mt*16 + (lane&15);
                int chunk = ks*2 + (lane>>4);
                unsigned addr = (unsigned)__cvta_generic_to_shared(&As[buf*ABUF + row*(BK+8) + chunk*8]);
                asm volatile("ldmatrix.sync.aligned.m8n8.x4.shared.b16 {%0,%1,%2,%3}, [%4];"
                    : "=r"(af[mt][0]),"=r"(af[mt][1]),"=r"(af[mt][2]),"=r"(af[mt][3]) : "r"(addr));
            }
            unsigned bfm[8][2];
            #pragma unroll
            for (int jn=0; jn<4; jn++){
                int row = ks*16 + (lane&15);
                int c = warp_n*8 + jn*2 + (lane>>4);
                unsigned addr = (unsigned)__cvta_generic_to_shared(&Bs[buf*BBUF + row*128 + ((c ^ (row&7))*8)]);
                unsigned r0,r1,r2,r3;
                asm volatile("ldmatrix.sync.aligned.m8n8.x4.trans.shared.b16 {%0,%1,%2,%3}, [%4];"
                    : "=r"(r0),"=r"(r1),"=r"(r2),"=r"(r3) : "r"(addr));
                bfm[jn*2][0]=r0;   bfm[jn*2][1]=r1;
                bfm[jn*2+1][0]=r2; bfm[jn*2+1][1]=r3;
            }
            #pragma unroll
            for (int mt=0; mt<2; mt++)
                #pragma unroll
                for (int nt=0; nt<8; nt++){
                    asm volatile("mma.sync.aligned.m16n8k16.row.col.f32.bf16.bf16.f32 "
                        "{%0,%1,%2,%3}, {%4,%5,%6,%7}, {%8,%9}, {%0,%1,%2,%3};"
                        : "+f"(acc[mt][nt][0]),"+f"(acc[mt][nt][1]),
                          "+f"(acc[mt][nt][2]),"+f"(acc[mt][nt][3])
                        : "r"(af[mt][0]),"r"(af[mt][1]),"r"(af[mt][2]),"r"(af[mt][3]),
                          "r"(bfm[nt][0]),"r"(bfm[nt][1]));
                }
        }
        __syncthreads();
    }

    #pragma unroll
    for (int mt=0; mt<2; mt++){
        #pragma unroll
        for (int i2=0; i2<2; i2++){
            long r = bm + warp_m*32 + mt*16 + (lane>>2) + i2*8;
            #pragma unroll
            for (int nt=0; nt<8; nt++){
                int cbase = bn + warp_n*64 + nt*8 + (lane&3)*2;
                #pragma unroll
                for (int j=0; j<2; j++){
                    int c = cbase + j;
                    if (c >= N) continue;
                    float v = acc[mt][nt][i2*2+j];
                    if (epi==2){ v += bias[c]; v = (v>20.f)? v : log1pf(expf(v)); }
                    else if (epi==3){ v += bias[c] + res[r*ldres + c]; }
                    if (C)  C[r*ldc + c] = v;
                    if (Ob) Ob[r*ldc + c] = f2b(v);
                }
            }
        }
    }
}

// ---------------- split-K combine: out = p0 + p1 + bias + x ---------------
__global__ void combine_kernel(const float* __restrict__ bias,
                               const float* __restrict__ x,
                               float* __restrict__ out){
    int i = (blockIdx.x*blockDim.x + threadIdx.x)*4;
    float4 a = *(const float4*)(&g_part[0][i]);
    float4 b = *(const float4*)(&g_part[1][i]);
    float4 r = *(const float4*)(x + i);
    int c = i & (DM-1);
    float4 o;
    o.x = a.x + b.x + r.x + bias[c];
    o.y = a.y + b.y + r.y + bias[c+1];
    o.z = a.z + b.z + r.z + bias[c+2];
    o.w = a.w + b.w + r.w + bias[c+3];
    *(float4*)(out + i) = o;
}

// ---------------- depthwise conv + SiLU (bf16 in/out) ----------------------
__global__ void conv_kernel(const float* __restrict__ wf, const float* __restrict__ biasf,
                            const float* __restrict__ wb, const float* __restrict__ biasb){
    int dir = blockIdx.z;
    const float* w    = dir ? wb : wf;
    const float* bias = dir ? biasb : biasf;
    int idx = blockIdx.x*blockDim.x + threadIdx.x;
    int d = idx & (DI-1);
    int t = (idx >> 10) & (LL-1);
    int b = idx >> 21;
    const bf16raw* xz = g_xz_bf[dir];
    float acc = bias[d];
    #pragma unroll
    for (int j=0;j<4;j++){
        int tt = (dir==0) ? (t-3+j) : (t+3-j);
        if (tt>=0 && tt<LL)
            acc = fmaf(w[d*4+j], b2f(xz[((long)(b*LL+tt)*2*DI) + d]), acc);
    }
    float s = acc / (1.f + __expf(-acc));
    g_xi_bf[dir][idx] = f2b(s);
}

// ---------------- selective scan: deferred-reduction, bf16 inputs ----------
struct ScanSmem {
    bf16raw dt[2][TCHUNK][CH];
    bf16raw xi[2][TCHUNK][CH];
    bf16raw z [2][TCHUNK][CH];
    float bc[2][TCHUNK][32];
    float p [TCHUNK][CH][17];
};

__global__ __launch_bounds__(256) void scan_kernel(
    const float* __restrict__ fA, const float* __restrict__ fD,
    const float* __restrict__ bA, const float* __restrict__ bD)
{
    extern __shared__ char smem_raw[];
    ScanSmem* S = reinterpret_cast<ScanSmem*>(smem_raw);

    int dir = blockIdx.z;
    int b   = blockIdx.y;
    int d0  = blockIdx.x * CH;
    const float* A_log = dir ? bA : fA;
    const float* Dp    = dir ? bD : fD;

    int tid  = threadIdx.x;
    int wid  = tid >> 5, lane = tid & 31;
    int half = lane >> 4, n = lane & 15;
    int dl   = wid*2 + half;

    float a    = -expf(A_log[(d0+dl)*DS + n]);
    float Dv_r = Dp[d0 + (tid & 15)];

    const bf16raw* dtp = g_dt_bf[dir];
    const bf16raw* xip = g_xi_bf[dir];
    const bf16raw* xzp = g_xz_bf[dir];
    const float*   bcp = g_xdbl[dir];

    const int NCH = LL / TCHUNK;

    auto loadChunk = [&](int c, int buf){
        if (tid < 192){   // dt/xi/z : 32 rows x 16 bf16 = 2 x 16B per row
            int arr = tid >> 6;
            int rem = tid & 63;
            int row = rem >> 1, seg = rem & 1;
            int trow = (dir==0) ? c*TCHUNK+row : (LL-1) - (c*TCHUNK+row);
            long tok = (long)b*LL + trow;
            if (arr==0)      cp16(&S->dt[buf][row][seg*8], dtp + tok*DI + d0 + seg*8);
            else if (arr==1) cp16(&S->xi[buf][row][seg*8], xip + tok*DI + d0 + seg*8);
            else             cp16(&S->z [buf][row][seg*8], xzp + tok*2*DI + DI + d0 + seg*8);
        }
        {   // B|C fp32 : 32 rows x 32 floats = 8 x 16B per row
            int row = tid >> 3, seg = tid & 7;
            int trow = (dir==0) ? c*TCHUNK+row : (LL-1) - (c*TCHUNK+row);
            long tok = (long)b*LL + trow;
            cp16(&S->bc[buf][row][seg*4], bcp + tok*64 + 32 + seg*4);
        }
    };

    float h = 0.f;
    loadChunk(0, 0);
    asm volatile("cp.async.commit_group;\n" ::: "memory");

    for (int c=0; c<NCH; c++){
        if (c+1 < NCH) loadChunk(c+1, (c+1)&1);
        asm volatile("cp.async.commit_group;\n" ::: "memory");
        asm volatile("cp.async.wait_group 1;\n" ::: "memory");
        __syncthreads();
        int buf = c & 1;

        #pragma unroll
        for (int s=0; s<TCHUNK; s++){
            float dtv = b2f(S->dt[buf][s][dl]);
            float xiv = b2f(S->xi[buf][s][dl]);
            float Bt  = S->bc[buf][s][n];
            float Ct  = S->bc[buf][s][16+n];
            float dA  = __expf(dtv * a);
            h = fmaf(dA, h, dtv*xiv*Bt);
            S->p[s][dl][n] = h * Ct;
        }
        __syncthreads();

        #pragma unroll
        for (int rep=0; rep<2; rep++){
            int o  = tid + rep*256;
            int s  = o >> 4, dlo = o & 15;
            float sum = 0.f;
            #pragma unroll
            for (int k=0;k<16;k++) sum += S->p[s][dlo][k];
            float xiv = b2f(S->xi[buf][s][dlo]);
            float zv  = b2f(S->z [buf][s][dlo]);
            float yv  = (sum + xiv*Dv_r) * zv / (1.f + __expf(-zv));
            int trow  = (dir==0) ? c*TCHUNK+s : (LL-1) - (c*TCHUNK+s);
            g_ycat_bf[((long)b*LL + trow)*2*DI + dir*DI + d0 + dlo] = f2b(yv);
        }
        __syncthreads();
    }
}

// ---------------- host launcher --------------------------------------------
extern "C" void kernel_launch(void* const* d_in, const int* in_sizes, int n_in,
                              void* d_out, int out_size){
    const float* x      = (const float*)d_in[0];
    const float* ln_g   = (const float*)d_in[1];
    const float* ln_b   = (const float*)d_in[2];
    const float* proj_w = (const float*)d_in[3];
    const float* proj_b = (const float*)d_in[4];
    const float* P[2][9];
    for (int dir=0; dir<2; dir++)
        for (int i=0;i<9;i++)
            P[dir][i] = (const float*)d_in[5 + dir*9 + i];

    float   *p_xdbl,*p_dtb;
    bf16raw *p_xzb,*p_dtbf,*p_xn,*p_xib,*p_xdblb,*p_ycat,*p_wcomb;
    float   *p_part;
    bf16raw *w_in,*w_xp,*w_dt,*w_cat,*w_pj;
    cudaGetSymbolAddress((void**)&p_xzb,   g_xz_bf);
    cudaGetSymbolAddress((void**)&p_xdbl,  g_xdbl);
    cudaGetSymbolAddress((void**)&p_dtbf,  g_dt_bf);
    cudaGetSymbolAddress((void**)&p_dtb,   g_dtb);
    cudaGetSymbolAddress((void**)&p_xn,    g_xn_bf);
    cudaGetSymbolAddress((void**)&p_xib,   g_xi_bf);
    cudaGetSymbolAddress((void**)&p_xdblb, g_xdbl_bf);
    cudaGetSymbolAddress((void**)&p_ycat,  g_ycat_bf);
    cudaGetSymbolAddress((void**)&p_wcomb, g_wcomb);
    cudaGetSymbolAddress((void**)&p_part,  g_part);
    cudaGetSymbolAddress((void**)&w_in,    g_w_in);
    cudaGetSymbolAddress((void**)&w_xp,    g_w_xp);
    cudaGetSymbolAddress((void**)&w_dt,    g_w_dt);
    cudaGetSymbolAddress((void**)&w_cat,   g_w_cat);
    cudaGetSymbolAddress((void**)&w_pj,    g_w_pj);

    const int SMEM64 = (2*(128*72) + 2*(64*128))*2;   // 69632
    const int SMEM32 = (2*(128*40) + 2*(32*128))*2;   // 36864
    cudaFuncSetAttribute(hgemm<64>, cudaFuncAttributeMaxDynamicSharedMemorySize, SMEM64);
    cudaFuncSetAttribute(hgemm<32>, cudaFuncAttributeMaxDynamicSharedMemorySize, SMEM32);

    // 0. fused weight conversion
    {
        CvtArgs a;
        const float* srcs[9] = {P[0][0], P[1][0], P[0][3], P[1][3], P[0][4],
                                P[1][4], P[0][8], P[1][8], proj_w};
        bf16raw* dsts[9] = {w_in, w_in+DM*2*DI, w_xp, w_xp+DI*64, w_dt,
                            w_dt+32*DI, w_cat, w_cat+DI*DM, w_pj};
        int sizes[9] = {DM*2*DI, DM*2*DI, DI*64, DI*64, 32*DI,
                        32*DI, DI*DM, DI*DM, DM*DM};
        int acc = 0;
        for (int i=0;i<9;i++){ a.s[i]=srcs[i]; a.d[i]=dsts[i]; a.off[i]=acc; acc += sizes[i]/4; }
        a.off[9] = acc;
        cvt_all_kernel<<<(acc+255)/256, 256>>>(a, acc);
    }
    pack_dtb_kernel<<<(2*DI+255)/256, 256>>>(P[0][5], P[1][5]);

    // 0c. fold: Wcomb = [f_out_w; b_out_w] @ proj_w   (2048 x 512, K=512) -> bf16
    hgemm<64><<<dim3(DM/128, 2*DI/128, 1), 256, SMEM64>>>(
        w_cat, 0, DM,
        w_pj,  0, DM,
        nullptr, 0, DM,
        p_wcomb, 0,
        DM, DM, nullptr, 0, nullptr, 0, 0);

    // 1. layernorm -> bf16
    ln_kernel<<<NTOK, 256>>>(x, ln_g, ln_b);

    // 2. in-proj: xz = xn @ in_w  (4096 x 2048, K=512) -> bf16 only
    hgemm<64><<<dim3(2*DI/128, NTOK/128, 2), 256, SMEM64>>>(
        p_xn, 0, DM,
        w_in, (long)DM*2*DI, 2*DI,
        nullptr, 0, 2*DI,
        p_xzb, (long)NTOK*2*DI,
        2*DI, DM, nullptr, 0, nullptr, 0, 0);

    // 3. conv + SiLU (bf16 -> bf16)
    conv_kernel<<<dim3(NTOK*DI/256,1,2), 256>>>(P[0][1], P[0][2], P[1][1], P[1][2]);

    // 4. x_proj: xdbl = xi @ xproj_w  (4096 x 64, K=1024), fp32 + bf16 shadow
    hgemm<64><<<dim3(1, NTOK/128, 2), 256, SMEM64>>>(
        p_xib, (long)NTOK*DI, DI,
        w_xp,  (long)DI*64,   64,
        p_xdbl,(long)NTOK*64, 64,
        p_xdblb,(long)NTOK*64,
        64, DI, nullptr, 0, nullptr, 0, 0);

    // 5. dt = softplus(xdbl[:, :32] @ dt_w + dt_b) -> bf16 only
    hgemm<32><<<dim3(DI/128, NTOK/128, 2), 256, SMEM32>>>(
        p_xdblb,(long)NTOK*64, 64,
        w_dt,   (long)32*DI,   DI,
        nullptr, 0, DI,
        p_dtbf, (long)NTOK*DI,
        DI, 32, p_dtb, DI, nullptr, 0, 2);

    // 6. selective scan (bf16 inputs) -> ycat bf16
    cudaFuncSetAttribute(scan_kernel, cudaFuncAttributeMaxDynamicSharedMemorySize,
                         (int)sizeof(ScanSmem));
    scan_kernel<<<dim3(DI/CH, BB, 2), 256, sizeof(ScanSmem)>>>(
        P[0][6], P[0][7], P[1][6], P[1][7]);

    // 7. out partials: split-K over K=2048 (z = K-half), 256 CTAs
    hgemm<64><<<dim3(DM/128, NTOK/128, 2), 256, SMEM64>>>(
        p_ycat, 1024, 2*DI,
        p_wcomb, (long)1024*DM, DM,
        p_part, (long)NTOK*DM, DM,
        nullptr, 0,
        DM, 1024, nullptr, 0, nullptr, 0, 0);

    // 8. combine: out = p0 + p1 + proj_b + x
    combine_kernel<<<NTOK*DM/1024, 256>>>(proj_b, x, (float*)d_out);
}

// round 9
// speedup vs baseline: 1.0698x; 1.0698x over previous
#include <cuda_runtime.h>
#include <cuda_bf16.h>
#include <stdint.h>
#include <math.h>

#define BB 2
#define LL 2048
#define DM 512
#define DI 1024
#define DS 16
#define NTOK (BB*LL)   // 4096
#define TCHUNK 32
#define CH 16

typedef unsigned short bf16raw;

static __device__ __forceinline__ bf16raw f2b(float x){
    __nv_bfloat16 h = __float2bfloat16_rn(x);
    return *reinterpret_cast<bf16raw*>(&h);
}
static __device__ __forceinline__ float b2f(bf16raw v){
    __nv_bfloat16 h = *reinterpret_cast<__nv_bfloat16*>(&v);
    return __bfloat162float(h);
}
static __device__ __forceinline__ void cp16(void* dst, const void* src){
    unsigned sa = (unsigned)__cvta_generic_to_shared(dst);
    asm volatile("cp.async.cg.shared.global [%0], [%1], 16;" :: "r"(sa), "l"(src));
}

// ---------------- scratch -------------------------------------------------
__device__ bf16raw g_xz_bf[2][NTOK*2*DI];    // in-proj out (xi|z), bf16
__device__ float   g_xi[2][NTOK*DI];         // conv+silu out fp32 (scan)
__device__ float   g_xdbl[2][NTOK*64];       // x_proj out fp32 (scan B/C)
__device__ float   g_dt[2][NTOK*DI];         // softplus(dt) fp32 (scan)
__device__ float   g_dtb[2][DI];
__device__ bf16raw g_xn_bf[NTOK*DM];
__device__ bf16raw g_xi_bf[2][NTOK*DI];      // conv out bf16 (GEMM2 A)
__device__ bf16raw g_xdbl_bf[2][NTOK*64];
__device__ bf16raw g_ycat_bf[NTOK*2*DI];
__device__ bf16raw g_wcomb[2*DI*DM];         // folded Wcat@Wproj [2048][512]
__device__ float   g_part2[4][NTOK*64];      // GEMM2 split-K partials (4 MB)
// bf16 weights
__device__ bf16raw g_w_in[2][DM*2*DI];
__device__ bf16raw g_w_xp[2][DI*64];
__device__ bf16raw g_w_dt[2][32*DI];
__device__ bf16raw g_w_cat[2*DI*DM];
__device__ bf16raw g_w_pj[DM*DM];

// ---------------- fused fp32 -> bf16 conversion ----------------------------
struct CvtArgs { const float* s[9]; bf16raw* d[9]; int off[10]; };

__global__ void cvt_all_kernel(CvtArgs a, int total4){
    int i = blockIdx.x*blockDim.x + threadIdx.x;
    if (i >= total4) return;
    int seg = 0;
    while (i >= a.off[seg+1]) seg++;
    int j = (i - a.off[seg])*4;
    float4 v = *(const float4*)(a.s[seg] + j);
    bf16raw* d = a.d[seg] + j;
    d[0]=f2b(v.x); d[1]=f2b(v.y); d[2]=f2b(v.z); d[3]=f2b(v.w);
}

__global__ void pack_dtb_kernel(const float* __restrict__ f, const float* __restrict__ b){
    int i = blockIdx.x*blockDim.x + threadIdx.x;
    if (i < DI)            g_dtb[0][i]    = f[i];
    else if (i < 2*DI)     g_dtb[1][i-DI] = b[i-DI];
}

// ---------------- layernorm: float4 + warp shuffle, 1 sync -----------------
__global__ __launch_bounds__(128) void ln_kernel(const float* __restrict__ x,
                          const float* __restrict__ g,
                          const float* __restrict__ b) {
    int row = blockIdx.x;
    int tid = threadIdx.x;                 // 128 threads, 4 floats each
    const float4* xr = (const float4*)(x + (long)row*DM);
    float4 v = xr[tid];
    float s = v.x+v.y+v.z+v.w;
    float q = v.x*v.x+v.y*v.y+v.z*v.z+v.w*v.w;
    #pragma unroll
    for (int o=16;o>0;o>>=1){
        s += __shfl_xor_sync(0xffffffffu, s, o);
        q += __shfl_xor_sync(0xffffffffu, q, o);
    }
    __shared__ float ss[4], sq[4];
    int wid = tid>>5, lane = tid&31;
    if (lane==0){ ss[wid]=s; sq[wid]=q; }
    __syncthreads();
    float S = ss[0]+ss[1]+ss[2]+ss[3];
    float Q = sq[0]+sq[1]+sq[2]+sq[3];
    float mu = S*(1.0f/DM);
    float var = Q*(1.0f/DM) - mu*mu;
    float rs = rsqrtf(var + 1e-5f);
    float4 gv = ((const float4*)g)[tid];
    float4 bv = ((const float4*)b)[tid];
    ushort4 o;
    o.x = f2b((v.x-mu)*rs*gv.x + bv.x);
    o.y = f2b((v.y-mu)*rs*gv.y + bv.y);
    o.z = f2b((v.z-mu)*rs*gv.z + bv.z);
    o.w = f2b((v.w-mu)*rs*gv.w + bv.w);
    ((ushort4*)(g_xn_bf + (long)row*DM))[tid] = o;
}

// ---------------- bf16 tensor-core GEMM, 128x128 tile, templated BK --------
// zsplit: if 1, z = zo*2 + zi with secondary strides sA2/sB2/sC2 for zi.
template<int BK>
__global__ __launch_bounds__(256) void hgemm(
    const bf16raw* __restrict__ Ag, long sA, int lda,
    const bf16raw* __restrict__ Bg, long sB, int ldb,
    float* __restrict__ Cg, long sC, int ldc,
    bf16raw* __restrict__ Obg, long sO,
    int N, int K,
    const float* __restrict__ biasg, long sbias,
    const float* __restrict__ res, int ldres,
    int epi,
    long sA2, long sB2, long sC2, int zsplit)
{
    int zo = zsplit ? (blockIdx.z>>1) : blockIdx.z;
    int zi = zsplit ? (blockIdx.z&1)  : 0;
    const bf16raw* A = Ag + sA*zo + sA2*zi;
    const bf16raw* B = Bg + sB*zo + sB2*zi;
    float* C   = Cg  ? Cg  + sC*zo + sC2*zi : nullptr;
    bf16raw* Ob = Obg ? Obg + sO*zo : nullptr;
    const float* bias = biasg ? biasg + sbias*zo : nullptr;

    extern __shared__ __align__(16) bf16raw sdyn[];
    const int ABUF = 128*(BK+8);
    const int BBUF = BK*128;
    bf16raw* As = sdyn;
    bf16raw* Bs = sdyn + 2*ABUF;

    int tid = threadIdx.x;
    int lane = tid & 31, wid = tid >> 5;
    int warp_m = wid & 3, warp_n = wid >> 2;
    int bm = blockIdx.y*128, bn = blockIdx.x*128;

    float acc[2][8][4];
    #pragma unroll
    for (int a=0;a<2;a++) for (int b2=0;b2<8;b2++) for (int c=0;c<4;c++) acc[a][b2][c]=0.f;

    int KT = K / BK;
    const int CPR = BK/8;

    auto loadTile = [&](int kt, int buf){
        int k0 = kt*BK;
        #pragma unroll
        for (int i=0;i<BK/16;i++){
            int q = tid + i*256;
            int r = q / CPR, c = q % CPR;
            const bf16raw* src = A + (long)(bm+r)*lda + k0 + c*8;
            unsigned sa = (unsigned)__cvta_generic_to_shared(&As[buf*ABUF + r*(BK+8) + c*8]);
            asm volatile("cp.async.cg.shared.global [%0], [%1], 16;\n" :: "r"(sa), "l"(src));
        }
        #pragma unroll
        for (int i=0;i<BK/16;i++){
            int q = tid + i*256;
            int r = q>>4, c = q&15;
            int gcol = bn + c*8;
            const bf16raw* src = B + (long)(k0+r)*ldb + gcol;
            unsigned sa = (unsigned)__cvta_generic_to_shared(&Bs[buf*BBUF + r*128 + ((c ^ (r&7))*8)]);
            int sz = (gcol < N) ? 16 : 0;
            asm volatile("cp.async.cg.shared.global [%0], [%1], 16, %2;\n" :: "r"(sa), "l"(src), "r"(sz));
        }
    };

    loadTile(0, 0);
    asm volatile("cp.async.commit_group;\n" ::: "memory");

    for (int kt=0; kt<KT; kt++){
        if (kt+1 < KT) loadTile(kt+1, (kt+1)&1);
        asm volatile("cp.async.commit_group;\n" ::: "memory");
        asm volatile("cp.async.wait_group 1;\n" ::: "memory");
        __syncthreads();
        int buf = kt & 1;

        #pragma unroll
        for (int ks=0; ks<BK/16; ks++){
            unsigned af[2][4];
            #pragma unroll
            for (int mt=0; mt<2; mt++){
                int row = warp_m*32 + mt*16 + (lane&15);
                int chunk = ks*2 + (lane>>4);
                unsigned addr = (unsigned)__cvta_generic_to_shared(&As[buf*ABUF + row*(BK+8) + chunk*8]);
                asm volatile("ldmatrix.sync.aligned.m8n8.x4.shared.b16 {%0,%1,%2,%3}, [%4];"
                    : "=r"(af[mt][0]),"=r"(af[mt][1]),"=r"(af[mt][2]),"=r"(af[mt][3]) : "r"(addr));
            }
            unsigned bfm[8][2];
            #pragma unroll
            for (int jn=0; jn<4; jn++){
                int row = ks*16 + (lane&15);
                int c = warp_n*8 + jn*2 + (lane>>4);
                unsigned addr = (unsigned)__cvta_generic_to_shared(&Bs[buf*BBUF + row*128 + ((c ^ (row&7))*8)]);
                unsigned r0,r1,r2,r3;
                asm volatile("ldmatrix.sync.aligned.m8n8.x4.trans.shared.b16 {%0,%1,%2,%3}, [%4];"
                    : "=r"(r0),"=r"(r1),"=r"(r2),"=r"(r3) : "r"(addr));
                bfm[jn*2][0]=r0;   bfm[jn*2][1]=r1;
                bfm[jn*2+1][0]=r2; bfm[jn*2+1][1]=r3;
            }
            #pragma unroll
            for (int mt=0; mt<2; mt++)
                #pragma unroll
                for (int nt=0; nt<8; nt++){
                    asm volatile("mma.sync.aligned.m16n8k16.row.col.f32.bf16.bf16.f32 "
                        "{%0,%1,%2,%3}, {%4,%5,%6,%7}, {%8,%9}, {%0,%1,%2,%3};"
                        : "+f"(acc[mt][nt][0]),"+f"(acc[mt][nt][1]),
                          "+f"(acc[mt][nt][2]),"+f"(acc[mt][nt][3])
                        : "r"(af[mt][0]),"r"(af[mt][1]),"r"(af[mt][2]),"r"(af[mt][3]),
                          "r"(bfm[nt][0]),"r"(bfm[nt][1]));
                }
        }
        __syncthreads();
    }

    #pragma unroll
    for (int mt=0; mt<2; mt++){
        #pragma unroll
        for (int i2=0; i2<2; i2++){
            long r = bm + warp_m*32 + mt*16 + (lane>>2) + i2*8;
            #pragma unroll
            for (int nt=0; nt<8; nt++){
                int cbase = bn + warp_n*64 + nt*8 + (lane&3)*2;
                #pragma unroll
                for (int j=0; j<2; j++){
                    int c = cbase + j;
                    if (c >= N) continue;
                    float v = acc[mt][nt][i2*2+j];
                    if (epi==2){ v += bias[c]; v = (v>20.f)? v : log1pf(expf(v)); }
                    else if (epi==3){ v += bias[c] + res[r*ldres + c]; }
                    if (C)  C[r*ldc + c] = v;
                    if (Ob) Ob[r*ldc + c] = f2b(v);
                }
            }
        }
    }
}

// ---------------- GEMM2 split-K combine: xdbl = p0+p1 (fp32 + bf16) -------
__global__ void combine2_kernel(){
    int i = (blockIdx.x*blockDim.x + threadIdx.x)*4;   // over 2*NTOK*64
    int dir = (i >= NTOK*64) ? 1 : 0;
    int j = i - dir*(NTOK*64);
    float4 a = *(const float4*)(&g_part2[dir*2+0][j]);
    float4 b = *(const float4*)(&g_part2[dir*2+1][j]);
    float4 o;
    o.x=a.x+b.x; o.y=a.y+b.y; o.z=a.z+b.z; o.w=a.w+b.w;
    *(float4*)(&g_xdbl[dir][j]) = o;
    ushort4 ob;
    ob.x=f2b(o.x); ob.y=f2b(o.y); ob.z=f2b(o.z); ob.w=f2b(o.w);
    *(ushort4*)(&g_xdbl_bf[dir][j]) = ob;
}

// ---------------- depthwise conv + SiLU (bf16 in, fp32+bf16 out) -----------
__global__ void conv_kernel(const float* __restrict__ wf, const float* __restrict__ biasf,
                            const float* __restrict__ wb, const float* __restrict__ biasb){
    int dir = blockIdx.z;
    const float* w    = dir ? wb : wf;
    const float* bias = dir ? biasb : biasf;
    int idx = blockIdx.x*blockDim.x + threadIdx.x;
    int d = idx & (DI-1);
    int t = (idx >> 10) & (LL-1);
    int b = idx >> 21;
    const bf16raw* xz = g_xz_bf[dir];
    float acc = bias[d];
    #pragma unroll
    for (int j=0;j<4;j++){
        int tt = (dir==0) ? (t-3+j) : (t+3-j);
        if (tt>=0 && tt<LL)
            acc = fmaf(w[d*4+j], b2f(xz[((long)(b*LL+tt)*2*DI) + d]), acc);
    }
    float s = acc / (1.f + __expf(-acc));
    g_xi[dir][idx]    = s;
    g_xi_bf[dir][idx] = f2b(s);
}

// ---------------- selective scan: deferred-reduction, fp32 hot path --------
struct ScanSmem {
    float   dt[2][TCHUNK][CH];
    float   xi[2][TCHUNK][CH];
    bf16raw z [2][TCHUNK][CH];
    float   bc[2][TCHUNK][32];
    float   p [TCHUNK][CH][17];
};

__global__ __launch_bounds__(256) void scan_kernel(
    const float* __restrict__ fA, const float* __restrict__ fD,
    const float* __restrict__ bA, const float* __restrict__ bD)
{
    extern __shared__ char smem_raw[];
    ScanSmem* S = reinterpret_cast<ScanSmem*>(smem_raw);

    int dir = blockIdx.z;
    int b   = blockIdx.y;
    int d0  = blockIdx.x * CH;
    const float* A_log = dir ? bA : fA;
    const float* Dp    = dir ? bD : fD;

    int tid  = threadIdx.x;
    int wid  = tid >> 5, lane = tid & 31;
    int half = lane >> 4, n = lane & 15;
    int dl   = wid*2 + half;

    float a    = -expf(A_log[(d0+dl)*DS + n]);
    float Dv_r = Dp[d0 + (tid & 15)];

    const float*   dtp = g_dt[dir];
    const float*   xip = g_xi[dir];
    const bf16raw* xzp = g_xz_bf[dir];
    const float*   bcp = g_xdbl[dir];

    const int NCH = LL / TCHUNK;

    auto loadChunk = [&](int c, int buf){
        if (tid < 128){   // dt/xi fp32 : 32 rows x 16 floats = 4 x 16B
            int row = tid >> 2, seg = tid & 3;
            int trow = (dir==0) ? c*TCHUNK+row : (LL-1) - (c*TCHUNK+row);
            long tok = (long)b*LL + trow;
            cp16(&S->dt[buf][row][seg*4], dtp + tok*DI + d0 + seg*4);
            cp16(&S->xi[buf][row][seg*4], xip + tok*DI + d0 + seg*4);
        } else if (tid < 192){   // z bf16 : 32 rows x 16 bf16 = 2 x 16B
            int rem = tid - 128;
            int row = rem >> 1, seg = rem & 1;
            int trow = (dir==0) ? c*TCHUNK+row : (LL-1) - (c*TCHUNK+row);
            long tok = (long)b*LL + trow;
            cp16(&S->z[buf][row][seg*8], xzp + tok*2*DI + DI + d0 + seg*8);
        }
        {   // B|C fp32 : 32 rows x 32 floats = 8 x 16B
            int row = tid >> 3, seg = tid & 7;
            int trow = (dir==0) ? c*TCHUNK+row : (LL-1) - (c*TCHUNK+row);
            long tok = (long)b*LL + trow;
            cp16(&S->bc[buf][row][seg*4], bcp + tok*64 + 32 + seg*4);
        }
    };

    float h = 0.f;
    loadChunk(0, 0);
    asm volatile("cp.async.commit_group;\n" ::: "memory");

    for (int c=0; c<NCH; c++){
        if (c+1 < NCH) loadChunk(c+1, (c+1)&1);
        asm volatile("cp.async.commit_group;\n" ::: "memory");
        asm volatile("cp.async.wait_group 1;\n" ::: "memory");
        __syncthreads();
        int buf = c & 1;

        #pragma unroll
        for (int s=0; s<TCHUNK; s++){
            float dtv = S->dt[buf][s][dl];
            float xiv = S->xi[buf][s][dl];
            float Bt  = S->bc[buf][s][n];
            float Ct  = S->bc[buf][s][16+n];
            float dA  = __expf(dtv * a);
            h = fmaf(dA, h, dtv*xiv*Bt);
            S->p[s][dl][n] = h * Ct;
        }
        __syncthreads();

        #pragma unroll
        for (int rep=0; rep<2; rep++){
            int o  = tid + rep*256;
            int s  = o >> 4, dlo = o & 15;
            float sum = 0.f;
            #pragma unroll
            for (int k=0;k<16;k++) sum += S->p[s][dlo][k];
            float xiv = S->xi[buf][s][dlo];
            float zv  = b2f(S->z[buf][s][dlo]);
            float yv  = (sum + xiv*Dv_r) * zv / (1.f + __expf(-zv));
            int trow  = (dir==0) ? c*TCHUNK+s : (LL-1) - (c*TCHUNK+s);
            g_ycat_bf[((long)b*LL + trow)*2*DI + dir*DI + d0 + dlo] = f2b(yv);
        }
        __syncthreads();
    }
}

// ---------------- host launcher --------------------------------------------
extern "C" void kernel_launch(void* const* d_in, const int* in_sizes, int n_in,
                              void* d_out, int out_size){
    const float* x      = (const float*)d_in[0];
    const float* ln_g   = (const float*)d_in[1];
    const float* ln_b   = (const float*)d_in[2];
    const float* proj_w = (const float*)d_in[3];
    const float* proj_b = (const float*)d_in[4];
    const float* P[2][9];
    for (int dir=0; dir<2; dir++)
        for (int i=0;i<9;i++)
            P[dir][i] = (const float*)d_in[5 + dir*9 + i];

    float   *p_xdbl,*p_dt,*p_dtb,*p_part2;
    bf16raw *p_xzb,*p_xn,*p_xib,*p_xdblb,*p_ycat,*p_wcomb;
    bf16raw *w_in,*w_xp,*w_dt,*w_cat,*w_pj;
    cudaGetSymbolAddress((void**)&p_xzb,   g_xz_bf);
    cudaGetSymbolAddress((void**)&p_xdbl,  g_xdbl);
    cudaGetSymbolAddress((void**)&p_dt,    g_dt);
    cudaGetSymbolAddress((void**)&p_dtb,   g_dtb);
    cudaGetSymbolAddress((void**)&p_part2, g_part2);
    cudaGetSymbolAddress((void**)&p_xn,    g_xn_bf);
    cudaGetSymbolAddress((void**)&p_xib,   g_xi_bf);
    cudaGetSymbolAddress((void**)&p_xdblb, g_xdbl_bf);
    cudaGetSymbolAddress((void**)&p_ycat,  g_ycat_bf);
    cudaGetSymbolAddress((void**)&p_wcomb, g_wcomb);
    cudaGetSymbolAddress((void**)&w_in,    g_w_in);
    cudaGetSymbolAddress((void**)&w_xp,    g_w_xp);
    cudaGetSymbolAddress((void**)&w_dt,    g_w_dt);
    cudaGetSymbolAddress((void**)&w_cat,   g_w_cat);
    cudaGetSymbolAddress((void**)&w_pj,    g_w_pj);

    const int SMEM64 = (2*(128*72) + 2*(64*128))*2;   // 69632
    const int SMEM32 = (2*(128*40) + 2*(32*128))*2;   // 36864
    cudaFuncSetAttribute(hgemm<64>, cudaFuncAttributeMaxDynamicSharedMemorySize, SMEM64);
    cudaFuncSetAttribute(hgemm<32>, cudaFuncAttributeMaxDynamicSharedMemorySize, SMEM32);

    // 0. fused weight conversion
    {
        CvtArgs a;
        const float* srcs[9] = {P[0][0], P[1][0], P[0][3], P[1][3], P[0][4],
                                P[1][4], P[0][8], P[1][8], proj_w};
        bf16raw* dsts[9] = {w_in, w_in+DM*2*DI, w_xp, w_xp+DI*64, w_dt,
                            w_dt+32*DI, w_cat, w_cat+DI*DM, w_pj};
        int sizes[9] = {DM*2*DI, DM*2*DI, DI*64, DI*64, 32*DI,
                        32*DI, DI*DM, DI*DM, DM*DM};
        int acc = 0;
        for (int i=0;i<9;i++){ a.s[i]=srcs[i]; a.d[i]=dsts[i]; a.off[i]=acc; acc += sizes[i]/4; }
        a.off[9] = acc;
        cvt_all_kernel<<<(acc+255)/256, 256>>>(a, acc);
    }
    pack_dtb_kernel<<<(2*DI+255)/256, 256>>>(P[0][5], P[1][5]);

    // 0c. fold: Wcomb = [f_out_w; b_out_w] @ proj_w   (2048 x 512, K=512)
    hgemm<64><<<dim3(DM/128, 2*DI/128, 1), 256, SMEM64>>>(
        w_cat, 0, DM,
        w_pj,  0, DM,
        nullptr, 0, DM,
        p_wcomb, 0,
        DM, DM, nullptr, 0, nullptr, 0, 0, 0,0,0,0);

    // 1. layernorm -> bf16
    ln_kernel<<<NTOK, 128>>>(x, ln_g, ln_b);

    // 2. in-proj: xz = xn @ in_w  (4096 x 2048, K=512) -> bf16
    hgemm<64><<<dim3(2*DI/128, NTOK/128, 2), 256, SMEM64>>>(
        p_xn, 0, DM,
        w_in, (long)DM*2*DI, 2*DI,
        nullptr, 0, 2*DI,
        p_xzb, (long)NTOK*2*DI,
        2*DI, DM, nullptr, 0, nullptr, 0, 0, 0,0,0,0);

    // 3. conv + SiLU (bf16 -> fp32 + bf16)
    conv_kernel<<<dim3(NTOK*DI/256,1,2), 256>>>(P[0][1], P[0][2], P[1][1], P[1][2]);

    // 4. x_proj split-K x2: z = dir*2 + khalf, 128 CTAs
    hgemm<64><<<dim3(1, NTOK/128, 4), 256, SMEM64>>>(
        p_xib, (long)NTOK*DI, DI,
        w_xp,  (long)DI*64,   64,
        p_part2, (long)2*NTOK*64, 64,
        nullptr, 0,
        64, 512, nullptr, 0, nullptr, 0, 0,
        /*sA2=*/512, /*sB2=*/(long)512*64, /*sC2=*/(long)NTOK*64, /*zsplit=*/1);

    // 4b. combine partials -> xdbl fp32 + bf16 shadow
    combine2_kernel<<<2*NTOK*64/1024, 256>>>();

    // 5. dt = softplus(xdbl[:, :32] @ dt_w + dt_b) -> fp32
    hgemm<32><<<dim3(DI/128, NTOK/128, 2), 256, SMEM32>>>(
        p_xdblb,(long)NTOK*64, 64,
        w_dt,   (long)32*DI,   DI,
        p_dt,   (long)NTOK*DI, DI,
        nullptr, 0,
        DI, 32, p_dtb, DI, nullptr, 0, 2, 0,0,0,0);

    // 6. selective scan -> ycat bf16
    cudaFuncSetAttribute(scan_kernel, cudaFuncAttributeMaxDynamicSharedMemorySize,
                         (int)sizeof(ScanSmem));
    scan_kernel<<<dim3(DI/CH, BB, 2), 256, sizeof(ScanSmem)>>>(
        P[0][6], P[0][7], P[1][6], P[1][7]);

    // 7. out = ycat @ Wcomb + proj_b + x  (4096 x 512, K=2048)
    hgemm<64><<<dim3(DM/128, NTOK/128, 1), 256, SMEM64>>>(
        p_ycat, 0, 2*DI,
        p_wcomb, 0, DM,
        (float*)d_out, 0, DM,
        nullptr, 0,
        DM, 2*DI, proj_b, 0, x, DM, 3, 0,0,0,0);
}